// round 3
// baseline (speedup 1.0000x reference)
#include <cuda_runtime.h>

// Problem constants
#define MM 4096
#define NN 4096
#define PLANE (MM * NN)

#define MAX_IT 20
#define F_SIGMA 14.285714285714285f   // 1/(7*0.01)
#define F_TAU 0.01f
#define F_LT 0.07f                    // LAMBDA_ROF * TAU
#define F_THETA 0.5f
#define F_INV_DENOM (1.0f / 1.07f)

// Ping-pong scratch (allocation-free rule: __device__ globals)
__device__ float g_x[2][PLANE];
__device__ float g_xt[2][PLANE];
__device__ float g_y[2][2 * PLANE];

__device__ __forceinline__ float clip1(float v) {
    return fminf(fmaxf(v, -1.0f), 1.0f);
}

// One fused primal-dual iteration.
//   dual:   y_new = clip(y + sigma * w * grad(x_tilde), -1, 1)
//   primal: x_new = (x + tau * div(w*y_new) + lambda*tau*img) / (1 + lambda*tau)
//   relax:  x_tilde_new = x_new + theta * (x_new - x)
// The divergence at (i,j) needs y_new at (i,j-1) and (i-1,j); those are
// recomputed from neighbor loads (cache hits) instead of a second kernel.
__global__ __launch_bounds__(256) void pd_iter(
    int first, int last, int in_b, int out_b,
    const float* __restrict__ img,
    const float* __restrict__ w,
    const float* __restrict__ y0,
    float* __restrict__ dout)
{
    const int j = blockIdx.x * blockDim.x + threadIdx.x;
    const int i = blockIdx.y;
    if (j >= NN) return;
    const int idx = i * NN + j;

    const float* __restrict__ x_in  = first ? img : g_x[in_b];
    const float* __restrict__ xt_in = first ? img : g_xt[in_b];
    const float* __restrict__ y0_in = first ? y0 : g_y[in_b];
    const float* __restrict__ y1_in = first ? (y0 + PLANE) : (g_y[in_b] + PLANE);
    const float* __restrict__ w0 = w;
    const float* __restrict__ w1 = w + PLANE;

    float* __restrict__ x_out  = g_x[out_b];
    float* __restrict__ xt_out = last ? dout : g_xt[out_b];
    float* __restrict__ y_out  = g_y[out_b];

    const float xt_c = xt_in[idx];
    const float w0c = w0[idx];
    const float w1c = w1[idx];

    // Dual update at (i,j)
    const float gx = (j < NN - 1) ? (xt_in[idx + 1] - xt_c) : 0.0f;
    const float gy = (i < MM - 1) ? (xt_in[idx + NN] - xt_c) : 0.0f;
    const float y0n = clip1(y0_in[idx] + F_SIGMA * w0c * gx);
    const float y1n = clip1(y1_in[idx] + F_SIGMA * w1c * gy);
    y_out[idx]         = y0n;
    y_out[idx + PLANE] = y1n;

    const float h_c = w0c * y0n;
    const float v_c = w1c * y1n;

    // Horizontal backward divergence term
    float dh;
    if (j == 0) {
        dh = h_c;
    } else {
        const float w0l = w0[idx - 1];
        const float y0l = clip1(y0_in[idx - 1] + F_SIGMA * w0l * (xt_c - xt_in[idx - 1]));
        const float h_l = w0l * y0l;
        dh = (j == NN - 1) ? -h_l : (h_c - h_l);
    }

    // Vertical backward divergence term
    float dv;
    if (i == 0) {
        dv = v_c;
    } else {
        const float w1u = w1[idx - NN];
        const float y1u = clip1(y1_in[idx - NN] + F_SIGMA * w1u * (xt_c - xt_in[idx - NN]));
        const float v_u = w1u * y1u;
        dv = (i == MM - 1) ? -v_u : (v_c - v_u);
    }

    // Primal update + over-relaxation
    const float xo = x_in[idx];
    const float xn = (xo + F_TAU * (dh + dv) + F_LT * img[idx]) * F_INV_DENOM;
    x_out[idx]  = xn;
    xt_out[idx] = xn + F_THETA * (xn - xo);
}

extern "C" void kernel_launch(void* const* d_in, const int* in_sizes, int n_in,
                              void* d_out, int out_size) {
    const float* img = (const float*)d_in[0];   // [1, 4096, 4096]
    const float* w   = (const float*)d_in[1];   // [2, 4096, 4096]
    const float* y0  = (const float*)d_in[2];   // [2, 4096, 4096]
    float* out = (float*)d_out;

    dim3 block(256, 1, 1);
    dim3 grid(NN / 256, MM, 1);

    for (int k = 0; k < MAX_IT; ++k) {
        const int first = (k == 0);
        const int last  = (k == MAX_IT - 1);
        const int in_b  = k & 1;
        const int out_b = (k + 1) & 1;
        pd_iter<<<grid, block>>>(first, last, in_b, out_b, img, w, y0, out);
    }
}